// round 2
// baseline (speedup 1.0000x reference)
#include <cuda_runtime.h>
#include <cuda_bf16.h>
#include <math.h>

// Problem dims
#define BB   2
#define SS   1024
#define VV   32000
#define DD   1024
#define RR   256
#define NCC  64
#define NKK  4096
#define KKK  8
#define HH   16
#define LL   4
#define DHH  64
#define BSZ  (BB*SS)          // 2048
#define NCR  (NCC*RR)         // 16384

// ---------------- scratch (device globals; allocation-free) ----------------
__device__ float g_x   [BSZ*DD];         // residual stream
__device__ float g_xln [BSZ*DD];         // layernorm output
__device__ float g_neuT[DD*NCR];         // neurons transposed [D, NC*R]  (64MB)
__device__ float g_T   [(long)BSZ*NCR];  // compress intermediate (134MB)
__device__ float g_rw  [BSZ*NCC];        // router weights
__device__ float g_h   [BSZ*RR];         // compressed rep
__device__ float g_Q   [BSZ*DD];
__device__ float g_K   [BSZ*DD];
__device__ float g_V   [BSZ*DD];
__device__ float g_sc  [(long)BB*HH*SS*SS]; // attention scores (134MB)
__device__ float g_ao  [BSZ*DD];         // attention output (concat heads)
__device__ float g_ms  [BSZ*NKK];        // memory scores
__device__ int   g_ti  [BSZ*KKK];        // topk idx
__device__ float g_tw  [BSZ*KKK];        // topk weights

// ---------------- SGEMM: C[M,N] = alpha * A[M,K] @ op(B) (+C) ----------------
// op(B) = B[K,N] (TB=false, row stride ldb) or B[N,K]^T (TB=true, row stride ldb)
// batched via blockIdx.z with element strides sA/sB/sC.
template<bool TB, bool ACC>
__global__ __launch_bounds__(256)
void sgemm_k(const float* __restrict__ A, const float* __restrict__ B,
             float* __restrict__ C, int M, int N, int K,
             int lda, int ldb, int ldc,
             long sA, long sB, long sC, float alpha)
{
    A += (long)blockIdx.z * sA;
    B += (long)blockIdx.z * sB;
    C += (long)blockIdx.z * sC;

    __shared__ float As[16][128];
    __shared__ float Bs[16][128];

    const int m0 = blockIdx.y * 128;
    const int n0 = blockIdx.x * 128;
    const int t  = threadIdx.x;
    const int tx = t & 15;     // 0..15 -> col group
    const int ty = t >> 4;     // 0..15 -> row group

    float acc[8][8];
#pragma unroll
    for (int i = 0; i < 8; i++)
#pragma unroll
        for (int j = 0; j < 8; j++) acc[i][j] = 0.f;

    for (int k0 = 0; k0 < K; k0 += 16) {
        // ---- load A tile [128 rows][16 k], K is always a multiple of 16 ----
#pragma unroll
        for (int i = 0; i < 2; i++) {
            int f   = t + i * 256;
            int row = f >> 2;
            int c4  = (f & 3) * 4;
            float4 v = make_float4(0.f, 0.f, 0.f, 0.f);
            if (m0 + row < M)
                v = *(const float4*)(A + (long)(m0 + row) * lda + k0 + c4);
            As[c4 + 0][row] = v.x; As[c4 + 1][row] = v.y;
            As[c4 + 2][row] = v.z; As[c4 + 3][row] = v.w;
        }
        // ---- load B tile [16 k][128 n] ----
        if (!TB) {
#pragma unroll
            for (int i = 0; i < 2; i++) {
                int f  = t + i * 256;
                int kr = f >> 5;
                int c4 = (f & 31) * 4;
                float4 v = make_float4(0.f, 0.f, 0.f, 0.f);
                if (n0 + c4 < N)   // N always multiple of 4 in this workload
                    v = *(const float4*)(B + (long)(k0 + kr) * ldb + n0 + c4);
                *(float4*)&Bs[kr][c4] = v;
            }
        } else {
#pragma unroll
            for (int i = 0; i < 2; i++) {
                int f  = t + i * 256;
                int n  = f >> 2;
                int c4 = (f & 3) * 4;
                float4 v = make_float4(0.f, 0.f, 0.f, 0.f);
                if (n0 + n < N)
                    v = *(const float4*)(B + (long)(n0 + n) * ldb + k0 + c4);
                Bs[c4 + 0][n] = v.x; Bs[c4 + 1][n] = v.y;
                Bs[c4 + 2][n] = v.z; Bs[c4 + 3][n] = v.w;
            }
        }
        __syncthreads();

#pragma unroll
        for (int kr = 0; kr < 16; kr++) {
            float a[8], b[8];
            *(float4*)(a)     = *(const float4*)&As[kr][ty * 8];
            *(float4*)(a + 4) = *(const float4*)&As[kr][ty * 8 + 4];
            *(float4*)(b)     = *(const float4*)&Bs[kr][tx * 8];
            *(float4*)(b + 4) = *(const float4*)&Bs[kr][tx * 8 + 4];
#pragma unroll
            for (int i = 0; i < 8; i++)
#pragma unroll
                for (int j = 0; j < 8; j++)
                    acc[i][j] += a[i] * b[j];
        }
        __syncthreads();
    }

#pragma unroll
    for (int i = 0; i < 8; i++) {
        int m = m0 + ty * 8 + i;
        if (m >= M) continue;
#pragma unroll
        for (int j = 0; j < 8; j++) {
            int n = n0 + tx * 8 + j;
            if (n >= N) continue;
            long o = (long)m * ldc + n;
            if (ACC) C[o] = C[o] + alpha * acc[i][j];
            else     C[o] = alpha * acc[i][j];
        }
    }
}

static inline void gemm(bool tb, bool accf,
                        const float* A, const float* B, float* C,
                        int M, int N, int K, int lda, int ldb, int ldc,
                        long sA, long sB, long sC, float alpha, int batch)
{
    dim3 g((N + 127) / 128, (M + 127) / 128, batch);
    if (tb) {
        if (accf) sgemm_k<true , true ><<<g, 256>>>(A, B, C, M, N, K, lda, ldb, ldc, sA, sB, sC, alpha);
        else      sgemm_k<true , false><<<g, 256>>>(A, B, C, M, N, K, lda, ldb, ldc, sA, sB, sC, alpha);
    } else {
        if (accf) sgemm_k<false, true ><<<g, 256>>>(A, B, C, M, N, K, lda, ldb, ldc, sA, sB, sC, alpha);
        else      sgemm_k<false, false><<<g, 256>>>(A, B, C, M, N, K, lda, ldb, ldc, sA, sB, sC, alpha);
    }
}

// ---------------- small kernels ----------------

// neuT[d*NCR + n*R + r] = neurons[(n*D + d)*R + r]; both sides r-contiguous.
__global__ void k_neuT(const float* __restrict__ nn, float* __restrict__ o)
{
    long i = (long)blockIdx.x * 256 + threadIdx.x;   // over D*NC*R = 16.8M
    int r  = (int)(i & (RR - 1));
    long t2 = i >> 8;
    int n  = (int)(t2 & (NCC - 1));
    int d  = (int)(t2 >> 6);
    o[i] = nn[((long)n * DD + d) * RR + r];
}

__global__ void k_embed(const int* __restrict__ tokens, const float* __restrict__ te,
                        const float* __restrict__ pe, float* __restrict__ x)
{
    int s = blockIdx.x;                 // 0..BSZ-1
    int tok = tokens[s];
    int sp  = s & (SS - 1);
    const float* tr = te + (long)tok * DD;
    const float* pr = pe + (long)sp * DD;
    float* xr = x + (long)s * DD;
    for (int d = threadIdx.x; d < DD; d += blockDim.x)
        xr[d] = tr[d] + pr[d];
}

__global__ void k_ln(const float* __restrict__ x, const float* __restrict__ g,
                     const float* __restrict__ b, float* __restrict__ y)
{
    int s = blockIdx.x, t = threadIdx.x;
    __shared__ float row[DD];
    __shared__ float red[256];
    const float* xr = x + (long)s * DD;
    float ls = 0.f;
    for (int d = t; d < DD; d += 256) { float v = xr[d]; row[d] = v; ls += v; }
    red[t] = ls; __syncthreads();
    for (int o = 128; o > 0; o >>= 1) { if (t < o) red[t] += red[t + o]; __syncthreads(); }
    float mean = red[0] * (1.f / DD); __syncthreads();
    float lv = 0.f;
    for (int d = t; d < DD; d += 256) { float dv = row[d] - mean; lv += dv * dv; }
    red[t] = lv; __syncthreads();
    for (int o = 128; o > 0; o >>= 1) { if (t < o) red[t] += red[t + o]; __syncthreads(); }
    float rstd = rsqrtf(red[0] * (1.f / DD) + 1e-5f);
    float* yr = y + (long)s * DD;
    for (int d = t; d < DD; d += 256)
        yr[d] = (row[d] - mean) * rstd * g[d] + b[d];
}

// softmax over rows of length 64 (router weights), in place
__global__ void k_smax64(float* __restrict__ a)
{
    int s = blockIdx.x, t = threadIdx.x;   // block = 64
    __shared__ float m[64];
    float v = a[(long)s * NCC + t];
    m[t] = v; __syncthreads();
    for (int o = 32; o > 0; o >>= 1) { if (t < o) m[t] = fmaxf(m[t], m[t + o]); __syncthreads(); }
    float mx = m[0]; __syncthreads();
    float e = expf(v - mx);
    m[t] = e; __syncthreads();
    for (int o = 32; o > 0; o >>= 1) { if (t < o) m[t] += m[t + o]; __syncthreads(); }
    a[(long)s * NCC + t] = e / m[0];
}

// h[s,r] = sum_n w[s,n] * T[s, n*R + r]
__global__ void k_combine(const float* __restrict__ T, const float* __restrict__ w,
                          float* __restrict__ h)
{
    int s = blockIdx.x, r = threadIdx.x;   // block = 256
    __shared__ float ws[NCC];
    if (r < NCC) ws[r] = w[(long)s * NCC + r];
    __syncthreads();
    const float* Trow = T + (long)s * NCR;
    float acc = 0.f;
#pragma unroll 8
    for (int n = 0; n < NCC; n++)
        acc += ws[n] * Trow[n * RR + r];
    h[(long)s * RR + r] = acc;
}

// causal row softmax over attention scores; rows of length S, zero out k>q
__global__ void k_asmax(float* __restrict__ sc)
{
    int rrow = blockIdx.x;                 // (b*H+h)*S + q
    int q = rrow & (SS - 1);
    int t = threadIdx.x;                   // 256
    __shared__ float row[SS];
    __shared__ float red[256];
    float* p = sc + (long)rrow * SS;
    int len = q + 1;
    float lm = -1e30f;
    for (int d = t; d < len; d += 256) { float v = p[d]; row[d] = v; lm = fmaxf(lm, v); }
    red[t] = lm; __syncthreads();
    for (int o = 128; o > 0; o >>= 1) { if (t < o) red[t] = fmaxf(red[t], red[t + o]); __syncthreads(); }
    float mx = red[0]; __syncthreads();
    float lsum = 0.f;
    for (int d = t; d < len; d += 256) { float e = expf(row[d] - mx); row[d] = e; lsum += e; }
    red[t] = lsum; __syncthreads();
    for (int o = 128; o > 0; o >>= 1) { if (t < o) red[t] += red[t + o]; __syncthreads(); }
    float inv = 1.f / red[0];
    for (int d = t; d < SS; d += 256)
        p[d] = (d < len) ? row[d] * inv : 0.f;
}

// top-8 of 4096 + softmax weights
__global__ void k_topk(const float* __restrict__ sc, int* __restrict__ ti, float* __restrict__ tw)
{
    __shared__ float row[NKK];             // 16KB
    __shared__ float rv[256];
    __shared__ int   ri[256];
    __shared__ float selv[KKK];
    __shared__ int   seli[KKK];
    int s = blockIdx.x, t = threadIdx.x;
    const float* p = sc + (long)s * NKK;
    for (int i = t; i < NKK; i += 256) row[i] = p[i];
    __syncthreads();
    for (int it = 0; it < KKK; it++) {
        float bm = -1e30f; int bi = NKK;
        for (int i = t; i < NKK; i += 256)
            if (row[i] > bm) { bm = row[i]; bi = i; }
        rv[t] = bm; ri[t] = bi; __syncthreads();
        for (int o = 128; o > 0; o >>= 1) {
            if (t < o) {
                if (rv[t + o] > rv[t] || (rv[t + o] == rv[t] && ri[t + o] < ri[t])) {
                    rv[t] = rv[t + o]; ri[t] = ri[t + o];
                }
            }
            __syncthreads();
        }
        if (t == 0) { selv[it] = rv[0]; seli[it] = ri[0]; row[ri[0]] = -1e30f; }
        __syncthreads();
    }
    if (t == 0) {
        float mx = selv[0];
        float e[KKK], sum = 0.f;
#pragma unroll
        for (int j = 0; j < KKK; j++) { e[j] = expf(selv[j] - mx); sum += e[j]; }
        float inv = 1.f / sum;
#pragma unroll
        for (int j = 0; j < KKK; j++) { tw[(long)s * KKK + j] = e[j] * inv; ti[(long)s * KKK + j] = seli[j]; }
    }
}

// x[s,:] += sum_j w[s,j] * kV[idx[s,j], :]
__global__ void k_memout(const float* __restrict__ kV, const int* __restrict__ ti,
                         const float* __restrict__ tw, float* __restrict__ x)
{
    int s = blockIdx.x, t = threadIdx.x;
    __shared__ int   idx[KKK];
    __shared__ float w[KKK];
    if (t < KKK) { idx[t] = ti[(long)s * KKK + t]; w[t] = tw[(long)s * KKK + t]; }
    __syncthreads();
    float* xr = x + (long)s * DD;
    for (int d = t; d < DD; d += 256) {
        float a = xr[d];
#pragma unroll
        for (int j = 0; j < KKK; j++)
            a += w[j] * kV[(long)idx[j] * DD + d];
        xr[d] = a;
    }
}

// ---------------- launch ----------------
extern "C" void kernel_launch(void* const* d_in, const int* in_sizes, int n_in,
                              void* d_out, int out_size)
{
    (void)in_sizes; (void)n_in; (void)out_size;
    const int*   tokens   = (const int*)  d_in[0];
    const float* tok_emb  = (const float*)d_in[1];
    const float* pos_emb  = (const float*)d_in[2];
    const float* neurons  = (const float*)d_in[3];
    const float* kK       = (const float*)d_in[4];
    const float* kV       = (const float*)d_in[5];
    const float* routerQ  = (const float*)d_in[6];
    const float* routerK  = (const float*)d_in[7];
    const float* routerV  = (const float*)d_in[8];
    const float* routerM  = (const float*)d_in[9];
    const float* expQ     = (const float*)d_in[10];
    const float* expK     = (const float*)d_in[11];
    const float* expV     = (const float*)d_in[12];
    const float* expO     = (const float*)d_in[13];
    const float* ln1_g    = (const float*)d_in[14];
    const float* ln1_b    = (const float*)d_in[15];
    const float* ln2_g    = (const float*)d_in[16];
    const float* ln2_b    = (const float*)d_in[17];
    const float* lnf_g    = (const float*)d_in[18];
    const float* lnf_b    = (const float*)d_in[19];
    float* out = (float*)d_out;

    float *px, *pxln, *pneuT, *pT, *prw, *ph, *pQ, *pK, *pV, *psc, *pao, *pms, *ptw;
    int *pti;
    cudaGetSymbolAddress((void**)&px,    g_x);
    cudaGetSymbolAddress((void**)&pxln,  g_xln);
    cudaGetSymbolAddress((void**)&pneuT, g_neuT);
    cudaGetSymbolAddress((void**)&pT,    g_T);
    cudaGetSymbolAddress((void**)&prw,   g_rw);
    cudaGetSymbolAddress((void**)&ph,    g_h);
    cudaGetSymbolAddress((void**)&pQ,    g_Q);
    cudaGetSymbolAddress((void**)&pK,    g_K);
    cudaGetSymbolAddress((void**)&pV,    g_V);
    cudaGetSymbolAddress((void**)&psc,   g_sc);
    cudaGetSymbolAddress((void**)&pao,   g_ao);
    cudaGetSymbolAddress((void**)&pms,   g_ms);
    cudaGetSymbolAddress((void**)&pti,   g_ti);
    cudaGetSymbolAddress((void**)&ptw,   g_tw);

    const float inv_sqrt_dh = 0.125f;   // 1/sqrt(64)
    const float inv_sqrt_r  = 0.0625f;  // 1/sqrt(256)

    // neurons -> [D, NC*R] (once per launch; constant data)
    k_neuT<<<(DD * NCC * RR) / 256, 256>>>(neurons, pneuT);
    // embeddings
    k_embed<<<BSZ, 256>>>(tokens, tok_emb, pos_emb, px);

    for (int l = 0; l < LL; l++) {
        const float* rQ = routerQ + (long)l * NCC * DD;
        const float* rK = routerK + (long)l * NCC * DD;
        const float* rV = routerV + (long)l * NCC * DD;
        const float* rM = routerM + (long)l * NCC * DD;
        const float* eQ = expQ + (long)l * DD * RR;
        const float* eK = expK + (long)l * DD * RR;
        const float* eV = expV + (long)l * DD * RR;
        const float* eO = expO + (long)l * DD * DD;

        // ---- attention sublayer ----
        k_ln<<<BSZ, 256>>>(px, ln1_g + l * DD, ln1_b + l * DD, pxln);
        // shared compress intermediate (router-independent)
        gemm(false, false, pxln, pneuT, pT, BSZ, NCR, DD, DD, NCR, NCR, 0, 0, 0, 1.f, 1);

        const float* routers[3] = { rQ, rK, rV };
        const float* exps[3]    = { eQ, eK, eV };
        float* dsts[3]          = { pQ, pK, pV };
        for (int c = 0; c < 3; c++) {
            gemm(true, false, pxln, routers[c], prw, BSZ, NCC, DD, DD, DD, NCC, 0, 0, 0, 1.f, 1);
            k_smax64<<<BSZ, 64>>>(prw);
            k_combine<<<BSZ, 256>>>(pT, prw, ph);
            gemm(true, false, ph, exps[c], dsts[c], BSZ, DD, RR, RR, RR, DD, 0, 0, 0, 1.f, 1);
        }

        // scores = Q K^T / 8, batched over heads (one launch per batch b)
        for (int b = 0; b < BB; b++) {
            gemm(true, false,
                 pQ + (long)b * SS * DD, pK + (long)b * SS * DD, psc + (long)b * HH * SS * SS,
                 SS, SS, DHH, DD, DD, SS,
                 DHH, DHH, (long)SS * SS, inv_sqrt_dh, HH);
        }
        k_asmax<<<BB * HH * SS, 256>>>(psc);
        // out = P @ V
        for (int b = 0; b < BB; b++) {
            gemm(false, false,
                 psc + (long)b * HH * SS * SS, pV + (long)b * SS * DD, pao + (long)b * SS * DD,
                 SS, DHH, SS, SS, DD, DD,
                 (long)SS * SS, DHH, DHH, 1.f, HH);
        }
        // x += out @ eO^T
        gemm(true, true, pao, eO, px, BSZ, DD, DD, DD, DD, DD, 0, 0, 0, 1.f, 1);

        // ---- memory sublayer ----
        k_ln<<<BSZ, 256>>>(px, ln2_g + l * DD, ln2_b + l * DD, pxln);
        gemm(false, false, pxln, pneuT, pT, BSZ, NCR, DD, DD, NCR, NCR, 0, 0, 0, 1.f, 1);
        gemm(true, false, pxln, rM, prw, BSZ, NCC, DD, DD, DD, NCC, 0, 0, 0, 1.f, 1);
        k_smax64<<<BSZ, 64>>>(prw);
        k_combine<<<BSZ, 256>>>(pT, prw, ph);
        // scores vs knowledge keys
        gemm(true, false, ph, kK, pms, BSZ, NKK, RR, RR, RR, NKK, 0, 0, 0, inv_sqrt_r, 1);
        k_topk<<<BSZ, 256>>>(pms, pti, ptw);
        k_memout<<<BSZ, 256>>>(kV, pti, ptw, px);
    }

    // final LN + tied lm head
    k_ln<<<BSZ, 256>>>(px, lnf_g, lnf_b, pxln);
    gemm(true, false, pxln, tok_emb, out, BSZ, VV, DD, DD, DD, VV, 0, 0, 0, 1.f, 1);
}

// round 6
// speedup vs baseline: 1.8959x; 1.8959x over previous
#include <cuda_runtime.h>
#include <cuda_bf16.h>
#include <cstdint>
#include <math.h>

// Problem dims
#define BB   2
#define SS   1024
#define VV   32000
#define DD   1024
#define RR   256
#define NCC  64
#define NKK  4096
#define KKK  8
#define HH   16
#define LL   4
#define DHH  64
#define BSZ  (BB*SS)          // 2048
#define NCR  (NCC*RR)         // 16384

// ---------------------------------------------------------------------------
// portable helpers (sm_80+ ISA only; NO tcgen05)
// ---------------------------------------------------------------------------
__device__ __forceinline__ uint32_t smem_to_u32(const void* p) {
    uint32_t a;
    asm("{ .reg .u64 t; cvta.to.shared.u64 t, %1; cvt.u32.u64 %0, t; }" : "=r"(a) : "l"(p));
    return a;
}
#define CP_ASYNC16(saddr, gptr) \
    asm volatile("cp.async.cg.shared.global [%0], [%1], 16;" :: "r"(saddr), "l"(gptr))
#define CP_COMMIT()  asm volatile("cp.async.commit_group;" ::: "memory")
#define CP_WAIT(n)   asm volatile("cp.async.wait_group %0;" :: "n"(n) : "memory")

__device__ __forceinline__ void mma16816(float* d, const uint32_t* a, const uint32_t* b) {
    asm volatile(
        "mma.sync.aligned.m16n8k16.row.col.f32.bf16.bf16.f32 "
        "{%0,%1,%2,%3}, {%4,%5,%6,%7}, {%8,%9}, {%0,%1,%2,%3};"
        : "+f"(d[0]), "+f"(d[1]), "+f"(d[2]), "+f"(d[3])
        : "r"(a[0]), "r"(a[1]), "r"(a[2]), "r"(a[3]), "r"(b[0]), "r"(b[1]));
}

// ---------------- scratch (device globals; allocation-free) ----------------
__device__ float g_x   [BSZ*DD];
__device__ float g_xln [BSZ*DD];
__device__ __nv_bfloat16 g_xlnh[BSZ*DD];
__device__ __nv_bfloat16 g_xlnl[BSZ*DD];
__device__ __nv_bfloat16 g_neuh[(long)NCR*DD];   // neurons^T [NC*R, D] hi
__device__ __nv_bfloat16 g_neul[(long)NCR*DD];   // lo
__device__ float g_T   [(long)BSZ*NCR];
__device__ float g_rw  [BSZ*NCC];
__device__ float g_h   [BSZ*RR];
__device__ __nv_bfloat16 g_hh[BSZ*RR];
__device__ __nv_bfloat16 g_hl[BSZ*RR];
__device__ float g_Q   [BSZ*DD];
__device__ float g_K   [BSZ*DD];
__device__ float g_Vt  [DD*BSZ];                 // V transposed [D, B*S]
__device__ float g_sc  [(long)BB*HH*SS*SS];
__device__ float g_ao  [BSZ*DD];
__device__ __nv_bfloat16 g_aoh[BSZ*DD];
__device__ __nv_bfloat16 g_aol[BSZ*DD];
__device__ float g_ms  [BSZ*NKK];
__device__ int   g_ti  [BSZ*KKK];
__device__ float g_tw  [BSZ*KKK];
// weight hi/lo splits
__device__ __nv_bfloat16 g_tembh[(long)VV*DD];
__device__ __nv_bfloat16 g_templ[(long)VV*DD];
__device__ __nv_bfloat16 g_eqh[LL*DD*RR], g_eql[LL*DD*RR];
__device__ __nv_bfloat16 g_ekh[LL*DD*RR], g_ekl[LL*DD*RR];
__device__ __nv_bfloat16 g_evh[LL*DD*RR], g_evl[LL*DD*RR];
__device__ __nv_bfloat16 g_eoh[LL*DD*DD], g_eol[LL*DD*DD];
__device__ __nv_bfloat16 g_kKh[NKK*RR],  g_kKl[NKK*RR];

// ---------------------------------------------------------------------------
// warp-MMA GEMM: C[M,N] (+)= alpha * (A[M,K] @ B[N,K]^T), bf16 hi/lo 3-pass.
// A row-major [M,K] stride lda; B [N,K] stride ldb (== col-major KxN).
// M%128==0, N%128==0, K%32==0, lda/ldb%8==0 required.
// grid = (N/128, M/128), 256 threads (8 warps: 4 in M x 2 in N).
// smem: double-buffered 128x32 bf16 tiles (pad to stride 40) for Ah,Al,Bh,Bl.
// ---------------------------------------------------------------------------
#define SKP 40                             // padded row stride (bf16 elems)
#define TILE_E (128*SKP)                   // elems per buffer
#define SMEM_MMA (4*2*TILE_E*2)            // bytes = 81920

__device__ __forceinline__ void stage_load(
    const __nv_bfloat16* __restrict__ Ah, const __nv_bfloat16* __restrict__ Al,
    const __nv_bfloat16* __restrict__ Bh, const __nv_bfloat16* __restrict__ Bl,
    uint32_t sAh, uint32_t sAl, uint32_t sBh, uint32_t sBl,
    int t, int m0, int n0, int k0, int lda, int ldb)
{
#pragma unroll
    for (int i = 0; i < 2; i++) {
        int f   = t + (i << 8);            // 0..511 : 16-byte chunks
        int row = f >> 2;                  // 0..127
        int cc  = (f & 3) << 3;            // elem col 0,8,16,24
        uint32_t so = (uint32_t)(row * SKP + cc) * 2;
        long ao_ = (long)(m0 + row) * lda + k0 + cc;
        long bo_ = (long)(n0 + row) * ldb + k0 + cc;
        CP_ASYNC16(sAh + so, Ah + ao_);
        CP_ASYNC16(sAl + so, Al + ao_);
        CP_ASYNC16(sBh + so, Bh + bo_);
        CP_ASYNC16(sBl + so, Bl + bo_);
    }
}

template<bool ACC>
__global__ __launch_bounds__(256)
void mma_gemm(const __nv_bfloat16* __restrict__ Ah, const __nv_bfloat16* __restrict__ Al,
              const __nv_bfloat16* __restrict__ Bh, const __nv_bfloat16* __restrict__ Bl,
              float* __restrict__ C, int K, int lda, int ldb, int ldc, float alpha)
{
    extern __shared__ __align__(16) char smem_raw[];
    uint32_t sbase = smem_to_u32(smem_raw);
    // layout: [2 stages][Ah, Al, Bh, Bl]
    const uint32_t stB = (uint32_t)TILE_E * 2;   // bytes per buffer
    uint32_t sAh0 = sbase,            sAl0 = sbase + 2*stB;
    uint32_t sBh0 = sbase + 4*stB,    sBl0 = sbase + 6*stB;

    const int t    = threadIdx.x;
    const int lane = t & 31;
    const int wid  = t >> 5;
    const int wm   = (wid & 3) << 5;   // warp m offset 0/32/64/96
    const int wn   = (wid >> 2) << 6;  // warp n offset 0/64
    const int m0   = blockIdx.y << 7;
    const int n0   = blockIdx.x << 7;

    float acc[2][8][4];
#pragma unroll
    for (int mt = 0; mt < 2; mt++)
#pragma unroll
        for (int nt = 0; nt < 8; nt++)
#pragma unroll
            for (int j = 0; j < 4; j++) acc[mt][nt][j] = 0.f;

    const int P = K >> 5;
    stage_load(Ah, Al, Bh, Bl, sAh0, sAl0, sBh0, sBl0, t, m0, n0, 0, lda, ldb);
    CP_COMMIT();

    const int rA = lane >> 2;          // 0..7
    const int cA = (lane & 3) << 1;    // 0,2,4,6

    for (int p = 0; p < P; p++) {
        int s = p & 1;
        if (p + 1 < P) {
            int s2 = (p + 1) & 1;
            stage_load(Ah, Al, Bh, Bl,
                       sAh0 + s2*stB, sAl0 + s2*stB, sBh0 + s2*stB, sBl0 + s2*stB,
                       t, m0, n0, (p + 1) << 5, lda, ldb);
            CP_COMMIT();
            CP_WAIT(1);
        } else {
            CP_WAIT(0);
        }
        __syncthreads();

        uint32_t bAh = sAh0 + s*stB, bAl = sAl0 + s*stB;
        uint32_t bBh = sBh0 + s*stB, bBl = sBl0 + s*stB;

#pragma unroll
        for (int ks = 0; ks < 2; ks++) {
            const int col = (ks << 4) + cA;   // k offset within 32
            uint32_t ah[2][4], al_[2][4], bh[8][2], bl[8][2];
#pragma unroll
            for (int mt = 0; mt < 2; mt++) {
                uint32_t r0 = (uint32_t)((wm + (mt << 4) + rA) * SKP + col) * 2;
                uint32_t r8 = r0 + 8u * SKP * 2;
                asm volatile("ld.shared.b32 %0, [%1];" : "=r"(ah[mt][0]) : "r"(bAh + r0));
                asm volatile("ld.shared.b32 %0, [%1];" : "=r"(ah[mt][1]) : "r"(bAh + r8));
                asm volatile("ld.shared.b32 %0, [%1];" : "=r"(ah[mt][2]) : "r"(bAh + r0 + 16));
                asm volatile("ld.shared.b32 %0, [%1];" : "=r"(ah[mt][3]) : "r"(bAh + r8 + 16));
                asm volatile("ld.shared.b32 %0, [%1];" : "=r"(al_[mt][0]) : "r"(bAl + r0));
                asm volatile("ld.shared.b32 %0, [%1];" : "=r"(al_[mt][1]) : "r"(bAl + r8));
                asm volatile("ld.shared.b32 %0, [%1];" : "=r"(al_[mt][2]) : "r"(bAl + r0 + 16));
                asm volatile("ld.shared.b32 %0, [%1];" : "=r"(al_[mt][3]) : "r"(bAl + r8 + 16));
            }
#pragma unroll
            for (int nt = 0; nt < 8; nt++) {
                uint32_t r0 = (uint32_t)((wn + (nt << 3) + rA) * SKP + col) * 2;
                asm volatile("ld.shared.b32 %0, [%1];" : "=r"(bh[nt][0]) : "r"(bBh + r0));
                asm volatile("ld.shared.b32 %0, [%1];" : "=r"(bh[nt][1]) : "r"(bBh + r0 + 16));
                asm volatile("ld.shared.b32 %0, [%1];" : "=r"(bl[nt][0]) : "r"(bBl + r0));
                asm volatile("ld.shared.b32 %0, [%1];" : "=r"(bl[nt][1]) : "r"(bBl + r0 + 16));
            }
#pragma unroll
            for (int mt = 0; mt < 2; mt++)
#pragma unroll
                for (int nt = 0; nt < 8; nt++) {
                    mma16816(acc[mt][nt], ah[mt],  bh[nt]);
                    mma16816(acc[mt][nt], ah[mt],  bl[nt]);
                    mma16816(acc[mt][nt], al_[mt], bh[nt]);
                }
        }
        __syncthreads();
    }

    // epilogue: c0,c1 -> C[m][n],C[m][n+1]; c2,c3 -> C[m+8][n],C[m+8][n+1]
#pragma unroll
    for (int mt = 0; mt < 2; mt++) {
        int r = m0 + wm + (mt << 4) + rA;
#pragma unroll
        for (int nt = 0; nt < 8; nt++) {
            int c = n0 + wn + (nt << 3) + cA;
            float* p0 = C + (long)r * ldc + c;
            float* p1 = p0 + 8 * ldc;
            float2 v0 = make_float2(acc[mt][nt][0] * alpha, acc[mt][nt][1] * alpha);
            float2 v1 = make_float2(acc[mt][nt][2] * alpha, acc[mt][nt][3] * alpha);
            if (ACC) {
                float2 o0 = *(float2*)p0, o1 = *(float2*)p1;
                v0.x += o0.x; v0.y += o0.y; v1.x += o1.x; v1.y += o1.y;
            }
            *(float2*)p0 = v0;
            *(float2*)p1 = v1;
        }
    }
}

// ---------------------------------------------------------------------------
// fp32 SGEMM (attention QK^T and PV) — batched.
// ---------------------------------------------------------------------------
template<bool TB>
__global__ __launch_bounds__(256)
void sgemm_k(const float* __restrict__ A, const float* __restrict__ B,
             float* __restrict__ C, int M, int N, int K,
             int lda, int ldb, int ldc,
             long sA, long sB, long sC, float alpha)
{
    A += (long)blockIdx.z * sA;
    B += (long)blockIdx.z * sB;
    C += (long)blockIdx.z * sC;

    __shared__ float As[16][128];
    __shared__ float Bs[16][128];

    const int m0 = blockIdx.y * 128;
    const int n0 = blockIdx.x * 128;
    const int t  = threadIdx.x;
    const int tx = t & 15;
    const int ty = t >> 4;

    float acc[8][8];
#pragma unroll
    for (int i = 0; i < 8; i++)
#pragma unroll
        for (int j = 0; j < 8; j++) acc[i][j] = 0.f;

    for (int k0 = 0; k0 < K; k0 += 16) {
#pragma unroll
        for (int i = 0; i < 2; i++) {
            int f   = t + i * 256;
            int row = f >> 2;
            int c4  = (f & 3) * 4;
            float4 v = make_float4(0.f, 0.f, 0.f, 0.f);
            if (m0 + row < M)
                v = *(const float4*)(A + (long)(m0 + row) * lda + k0 + c4);
            As[c4 + 0][row] = v.x; As[c4 + 1][row] = v.y;
            As[c4 + 2][row] = v.z; As[c4 + 3][row] = v.w;
        }
        if (!TB) {
#pragma unroll
            for (int i = 0; i < 2; i++) {
                int f  = t + i * 256;
                int kr = f >> 5;
                int c4 = (f & 31) * 4;
                float4 v = make_float4(0.f, 0.f, 0.f, 0.f);
                if (n0 + c4 < N)
                    v = *(const float4*)(B + (long)(k0 + kr) * ldb + n0 + c4);
                *(float4*)&Bs[kr][c4] = v;
            }
        } else {
#pragma unroll
            for (int i = 0; i < 2; i++) {
                int f  = t + i * 256;
                int n  = f >> 2;
                int c4 = (f & 3) * 4;
                float4 v = make_float4(0.f, 0.f, 0.f, 0.f);
                if (n0 + n < N)
                    v = *(const float4*)(B + (long)(n0 + n) * ldb + k0 + c4);
                Bs[c4 + 0][n] = v.x; Bs[c4 + 1][n] = v.y;
                Bs[c4 + 2][n] = v.z; Bs[c4 + 3][n] = v.w;
            }
        }
        __syncthreads();
#pragma unroll
        for (int kr = 0; kr < 16; kr++) {
            float a[8], b[8];
            *(float4*)(a)     = *(const float4*)&As[kr][ty * 8];
            *(float4*)(a + 4) = *(const float4*)&As[kr][ty * 8 + 4];
            *(float4*)(b)     = *(const float4*)&Bs[kr][tx * 8];
            *(float4*)(b + 4) = *(const float4*)&Bs[kr][tx * 8 + 4];
#pragma unroll
            for (int i = 0; i < 8; i++)
#pragma unroll
                for (int j = 0; j < 8; j++)
                    acc[i][j] += a[i] * b[j];
        }
        __syncthreads();
    }
#pragma unroll
    for (int i = 0; i < 8; i++) {
        int m = m0 + ty * 8 + i;
        if (m >= M) continue;
#pragma unroll
        for (int j = 0; j < 8; j++) {
            int n = n0 + tx * 8 + j;
            if (n >= N) continue;
            C[(long)m * ldc + n] = alpha * acc[i][j];
        }
    }
}

// ---------------------------------------------------------------------------
// small kernels
// ---------------------------------------------------------------------------
__device__ __forceinline__ void split_hl(float v, __nv_bfloat16* ph, __nv_bfloat16* pl) {
    __nv_bfloat16 h = __float2bfloat16(v);
    *ph = h;
    *pl = __float2bfloat16(v - __bfloat162float(h));
}

// neurons [NC,D,R] -> neuT [NC*R, D] bf16 hi/lo (tiled transpose)
__global__ void k_neuT(const float* __restrict__ nn,
                       __nv_bfloat16* __restrict__ oh, __nv_bfloat16* __restrict__ ol)
{
    __shared__ float tile[32][33];
    int d0 = blockIdx.x * 32, r0 = blockIdx.y * 32, n = blockIdx.z;
    int tx = threadIdx.x, ty = threadIdx.y;
#pragma unroll
    for (int j = 0; j < 32; j += 8)
        tile[ty + j][tx] = nn[((long)n * DD + d0 + ty + j) * RR + r0 + tx];
    __syncthreads();
#pragma unroll
    for (int j = 0; j < 32; j += 8) {
        float v = tile[tx][ty + j];
        long o = ((long)(n * RR + r0 + ty + j)) * DD + d0 + tx;
        split_hl(v, oh + o, ol + o);
    }
}

__global__ void k_cvt(const float* __restrict__ x, __nv_bfloat16* __restrict__ h,
                      __nv_bfloat16* __restrict__ l, long n)
{
    long i = (long)blockIdx.x * 256 + threadIdx.x;
    if (i < n) split_hl(x[i], h + i, l + i);
}

__global__ void k_embed(const int* __restrict__ tokens, const float* __restrict__ te,
                        const float* __restrict__ pe, float* __restrict__ x)
{
    int s = blockIdx.x;
    int tok = tokens[s];
    int sp  = s & (SS - 1);
    const float* tr = te + (long)tok * DD;
    const float* pr = pe + (long)sp * DD;
    float* xr = x + (long)s * DD;
    for (int d = threadIdx.x; d < DD; d += blockDim.x)
        xr[d] = tr[d] + pr[d];
}

__global__ void k_ln(const float* __restrict__ x, const float* __restrict__ g,
                     const float* __restrict__ b, float* __restrict__ y,
                     __nv_bfloat16* __restrict__ yh, __nv_bfloat16* __restrict__ yl)
{
    int s = blockIdx.x, t = threadIdx.x;
    __shared__ float row[DD];
    __shared__ float red[256];
    const float* xr = x + (long)s * DD;
    float ls = 0.f;
    for (int d = t; d < DD; d += 256) { float v = xr[d]; row[d] = v; ls += v; }
    red[t] = ls; __syncthreads();
    for (int o = 128; o > 0; o >>= 1) { if (t < o) red[t] += red[t + o]; __syncthreads(); }
    float mean = red[0] * (1.f / DD); __syncthreads();
    float lv = 0.f;
    for (int d = t; d < DD; d += 256) { float dv = row[d] - mean; lv += dv * dv; }
    red[t] = lv; __syncthreads();
    for (int o = 128; o > 0; o >>= 1) { if (t < o) red[t] += red[t + o]; __syncthreads(); }
    float rstd = rsqrtf(red[0] * (1.f / DD) + 1e-5f);
    for (int d = t; d < DD; d += 256) {
        float v = (row[d] - mean) * rstd * g[d] + b[d];
        long o = (long)s * DD + d;
        y[o] = v;
        split_hl(v, yh + o, yl + o);
    }
}

// router logits: rw[s, n] = sum_d xln[s,d] * R_[n,d]  (N = 64)
__global__ void k_router(const float* __restrict__ xln, const float* __restrict__ R_,
                         float* __restrict__ rw)
{
    __shared__ float xs[8][DD];
    int s0 = blockIdx.x * 8;
    for (int i = threadIdx.x; i < 2048; i += 256) {
        int r = i >> 8, c = (i & 255) << 2;
        *(float4*)&xs[r][c] = *(const float4*)(xln + (long)(s0 + r) * DD + c);
    }
    __syncthreads();
    int w = threadIdx.x >> 5, lane = threadIdx.x & 31;
    for (int n = 0; n < NCC; n++) {
        const float* rr = R_ + (long)n * DD;
        float acc = 0.f;
        for (int k = lane * 4; k < DD; k += 128) {
            float4 rv = *(const float4*)(rr + k);
            float4 xv = *(const float4*)&xs[w][k];
            acc += rv.x * xv.x + rv.y * xv.y + rv.z * xv.z + rv.w * xv.w;
        }
#pragma unroll
        for (int o = 16; o; o >>= 1) acc += __shfl_xor_sync(0xFFFFFFFFu, acc, o);
        if (!lane) rw[(long)(s0 + w) * NCC + n] = acc;
    }
}

__global__ void k_smax64(float* __restrict__ a)
{
    int s = blockIdx.x, t = threadIdx.x;
    __shared__ float m[64];
    float v = a[(long)s * NCC + t];
    m[t] = v; __syncthreads();
    for (int o = 32; o > 0; o >>= 1) { if (t < o) m[t] = fmaxf(m[t], m[t + o]); __syncthreads(); }
    float mx = m[0]; __syncthreads();
    float e = expf(v - mx);
    m[t] = e; __syncthreads();
    for (int o = 32; o > 0; o >>= 1) { if (t < o) m[t] += m[t + o]; __syncthreads(); }
    a[(long)s * NCC + t] = e / m[0];
}

// h[s,r] = sum_n w[s,n] * T[s, n*R + r]  (+ bf16 hi/lo split)
__global__ void k_combine(const float* __restrict__ T, const float* __restrict__ w,
                          float* __restrict__ h, __nv_bfloat16* __restrict__ hh,
                          __nv_bfloat16* __restrict__ hl)
{
    int s = blockIdx.x, r = threadIdx.x;
    __shared__ float ws[NCC];
    if (r < NCC) ws[r] = w[(long)s * NCC + r];
    __syncthreads();
    const float* Trow = T + (long)s * NCR;
    float acc = 0.f;
#pragma unroll 8
    for (int n = 0; n < NCC; n++)
        acc += ws[n] * Trow[n * RR + r];
    long o = (long)s * RR + r;
    h[o] = acc;
    split_hl(acc, hh + o, hl + o);
}

__global__ void k_asmax(float* __restrict__ sc)
{
    int rrow = blockIdx.x;
    int q = rrow & (SS - 1);
    int t = threadIdx.x;
    __shared__ float row[SS];
    __shared__ float red[256];
    float* p = sc + (long)rrow * SS;
    int len = q + 1;
    float lm = -1e30f;
    for (int d = t; d < len; d += 256) { float v = p[d]; row[d] = v; lm = fmaxf(lm, v); }
    red[t] = lm; __syncthreads();
    for (int o = 128; o > 0; o >>= 1) { if (t < o) red[t] = fmaxf(red[t], red[t + o]); __syncthreads(); }
    float mx = red[0]; __syncthreads();
    float lsum = 0.f;
    for (int d = t; d < len; d += 256) { float e = expf(row[d] - mx); row[d] = e; lsum += e; }
    red[t] = lsum; __syncthreads();
    for (int o = 128; o > 0; o >>= 1) { if (t < o) red[t] += red[t + o]; __syncthreads(); }
    float inv = 1.f / red[0];
    for (int d = t; d < SS; d += 256)
        p[d] = (d < len) ? row[d] * inv : 0.f;
}

__global__ void k_topk(const float* __restrict__ sc, int* __restrict__ ti, float* __restrict__ tw)
{
    __shared__ float row[NKK];
    __shared__ float rv[256];
    __shared__ int   ri[256];
    __shared__ float selv[KKK];
    __shared__ int   seli[KKK];
    int s = blockIdx.x, t = threadIdx.x;
    const float* p = sc + (long)s * NKK;
    for (int i = t; i < NKK; i += 256) row[i] = p[i];
    __syncthreads();
    for (int it = 0; it < KKK; it++) {
        float bm = -1e30f; int bi = NKK;
        for (int i = t; i < NKK; i += 256)
            if (row[i] > bm) { bm = row[i]; bi = i; }
        rv[t] = bm; ri[t] = bi; __syncthreads();
        for (int o = 128; o > 0; o >>= 1) {
            if (t < o) {
                if (rv[t + o] > rv[t] || (rv[t + o] == rv[t] && ri[t + o] < ri[t])) {
                    rv[t] = rv[t + o]; ri[t] = ri[t + o];
                }
            }
            __syncthreads();
        }
        if (t == 0) { selv[it] = rv[0]; seli[it] = ri[0]; row[ri[0]] = -1e30f; }
        __syncthreads();
    }
    if (t == 0) {
        float mx = selv[0];
        float e[KKK], sum = 0.f;
#pragma unroll
        for (int j = 0; j < KKK; j++) { e[j] = expf(selv[j] - mx); sum += e[j]; }
        float inv = 1.f / sum;
#pragma unroll
        for (int j = 0; j < KKK; j++) { tw[(long)s * KKK + j] = e[j] * inv; ti[(long)s * KKK + j] = seli[j]; }
    }
}

__global__ void k_memout(const float* __restrict__ kV, const int* __restrict__ ti,
                         const float* __restrict__ tw, float* __restrict__ x)
{
    int s = blockIdx.x, t = threadIdx.x;
    __shared__ int   idx[KKK];
    __shared__ float w[KKK];
    if (t < KKK) { idx[t] = ti[(long)s * KKK + t]; w[t] = tw[(long)s * KKK + t]; }
    __syncthreads();
    float* xr = x + (long)s * DD;
    for (int d = t; d < DD; d += 256) {
        float a = xr[d];
#pragma unroll
        for (int j = 0; j < KKK; j++)
            a += w[j] * kV[(long)idx[j] * DD + d];
        xr[d] = a;
    }
}

// ---------------------------------------------------------------------------
extern "C" void kernel_launch(void* const* d_in, const int* in_sizes, int n_in,
                              void* d_out, int out_size)
{
    (void)in_sizes; (void)n_in; (void)out_size;
    const int*   tokens   = (const int*)  d_in[0];
    const float* tok_emb  = (const float*)d_in[1];
    const float* pos_emb  = (const float*)d_in[2];
    const float* neurons  = (const float*)d_in[3];
    const float* kK       = (const float*)d_in[4];
    const float* kV       = (const float*)d_in[5];
    const float* routerQ  = (const float*)d_in[6];
    const float* routerK  = (const float*)d_in[7];
    const float* routerV  = (const float*)d_in[8];
    const float* routerM  = (const float*)d_in[9];
    const float* expQ     = (const float*)d_in[10];
    const float* expK     = (const float*)d_in[11];
    const float* expV     = (const float*)d_in[12];
    const float* expO     = (const float*)d_in[13];
    const float* ln1_g    = (const float*)d_in[14];
    const float* ln1_b    = (const float*)d_in[15];
    const float* ln2_g    = (const float*)d_in[16];
    const float* ln2_b    = (const float*)d_in[17];
    const float* lnf_g    = (const float*)d_in[18];
    const float* lnf_b    = (const float*)d_in[19];
    float* out = (float*)d_out;

    float *px, *pxln, *pT, *prw, *ph, *pQ, *pK, *pVt, *psc, *pao, *pms, *ptw;
    int *pti;
    __nv_bfloat16 *pxlnh, *pxlnl, *pneuh, *pneul, *phh, *phl, *paoh, *paol;
    __nv_bfloat16 *ptembh, *ptembl, *peqh, *peql, *pekh, *pekl, *pevh, *pevl, *peoh, *peol, *pkKh, *pkKl;
    cudaGetSymbolAddress((void**)&px,    g_x);
    cudaGetSymbolAddress((void**)&pxln,  g_xln);
    cudaGetSymbolAddress((void**)&pxlnh, g_xlnh);
    cudaGetSymbolAddress((void**)&pxlnl, g_xlnl);
    cudaGetSymbolAddress((void**)&pneuh, g_neuh);
    cudaGetSymbolAddress((void**)&pneul, g_neul);
    cudaGetSymbolAddress((void**)&pT,    g_T);
    cudaGetSymbolAddress((void**)&prw,   g_rw);
    cudaGetSymbolAddress((void**)&ph,    g_h);
    cudaGetSymbolAddress((void**)&phh,   g_hh);
    cudaGetSymbolAddress((void**)&phl,   g_hl);
    cudaGetSymbolAddress((void**)&pQ,    g_Q);
    cudaGetSymbolAddress((void**)&pK,    g_K);
    cudaGetSymbolAddress((void**)&pVt,   g_Vt);
    cudaGetSymbolAddress((void**)&psc,   g_sc);
    cudaGetSymbolAddress((void**)&pao,   g_ao);
    cudaGetSymbolAddress((void**)&paoh,  g_aoh);
    cudaGetSymbolAddress((void**)&paol,  g_aol);
    cudaGetSymbolAddress((void**)&pms,   g_ms);
    cudaGetSymbolAddress((void**)&pti,   g_ti);
    cudaGetSymbolAddress((void**)&ptw,   g_tw);
    cudaGetSymbolAddress((void**)&ptembh, g_tembh);
    cudaGetSymbolAddress((void**)&ptembl, g_templ);
    cudaGetSymbolAddress((void**)&peqh,  g_eqh);
    cudaGetSymbolAddress((void**)&peql,  g_eql);
    cudaGetSymbolAddress((void**)&pekh,  g_ekh);
    cudaGetSymbolAddress((void**)&pekl,  g_ekl);
    cudaGetSymbolAddress((void**)&pevh,  g_evh);
    cudaGetSymbolAddress((void**)&pevl,  g_evl);
    cudaGetSymbolAddress((void**)&peoh,  g_eoh);
    cudaGetSymbolAddress((void**)&peol,  g_eol);
    cudaGetSymbolAddress((void**)&pkKh,  g_kKh);
    cudaGetSymbolAddress((void**)&pkKl,  g_kKl);

    cudaFuncSetAttribute(mma_gemm<false>, cudaFuncAttributeMaxDynamicSharedMemorySize, SMEM_MMA);
    cudaFuncSetAttribute(mma_gemm<true>,  cudaFuncAttributeMaxDynamicSharedMemorySize, SMEM_MMA);

    const float inv_sqrt_dh = 0.125f;
    const float inv_sqrt_r  = 0.0625f;

    // one-time weight preprocessing (per launch; constant data)
    k_neuT<<<dim3(DD/32, RR/32, NCC), dim3(32, 8)>>>(neurons, pneuh, pneul);
    {
        long n;
        n = (long)VV * DD;     k_cvt<<<(unsigned)((n + 255) / 256), 256>>>(tok_emb, ptembh, ptembl, n);
        n = (long)LL * DD * RR;
        k_cvt<<<(unsigned)((n + 255) / 256), 256>>>(expQ, peqh, peql, n);
        k_cvt<<<(unsigned)((n + 255) / 256), 256>>>(expK, pekh, pekl, n);
        k_cvt<<<(unsigned)((n + 255) / 256), 256>>>(expV, pevh, pevl, n);
        n = (long)LL * DD * DD; k_cvt<<<(unsigned)((n + 255) / 256), 256>>>(expO, peoh, peol, n);
        n = (long)NKK * RR;     k_cvt<<<(unsigned)((n + 255) / 256), 256>>>(kK, pkKh, pkKl, n);
    }
    k_embed<<<BSZ, 256>>>(tokens, tok_emb, pos_emb, px);

    for (int l = 0; l < LL; l++) {
        const float* rQ = routerQ + (long)l * NCC * DD;
        const float* rK = routerK + (long)l * NCC * DD;
        const float* rV = routerV + (long)l * NCC * DD;
        const float* rM = routerM + (long)l * NCC * DD;
        long eoff = (long)l * DD * RR;
        long ooff = (long)l * DD * DD;

        // ---- attention sublayer ----
        k_ln<<<BSZ, 256>>>(px, ln1_g + l * DD, ln1_b + l * DD, pxln, pxlnh, pxlnl);
        // shared compress: T[2048,16384] = xln @ neuT^T
        mma_gemm<false><<<dim3(NCR/128, BSZ/128), 256, SMEM_MMA>>>(
            pxlnh, pxlnl, pneuh, pneul, pT, DD, DD, DD, NCR, 1.f);

        // Q
        k_router<<<BSZ/8, 256>>>(pxln, rQ, prw);
        k_smax64<<<BSZ, 64>>>(prw);
        k_combine<<<BSZ, 256>>>(pT, prw, ph, phh, phl);
        mma_gemm<false><<<dim3(DD/128, BSZ/128), 256, SMEM_MMA>>>(
            phh, phl, peqh + eoff, peql + eoff, pQ, RR, RR, RR, DD, 1.f);
        // K
        k_router<<<BSZ/8, 256>>>(pxln, rK, prw);
        k_smax64<<<BSZ, 64>>>(prw);
        k_combine<<<BSZ, 256>>>(pT, prw, ph, phh, phl);
        mma_gemm<false><<<dim3(DD/128, BSZ/128), 256, SMEM_MMA>>>(
            phh, phl, pekh + eoff, pekl + eoff, pK, RR, RR, RR, DD, 1.f);
        // V (produced transposed: Vt[D, B*S] = ev @ h^T)
        k_router<<<BSZ/8, 256>>>(pxln, rV, prw);
        k_smax64<<<BSZ, 64>>>(prw);
        k_combine<<<BSZ, 256>>>(pT, prw, ph, phh, phl);
        mma_gemm<false><<<dim3(BSZ/128, DD/128), 256, SMEM_MMA>>>(
            pevh + eoff, pevl + eoff, phh, phl, pVt, RR, RR, RR, BSZ, 1.f);

        // scores = Q K^T / 8
        for (int b = 0; b < BB; b++) {
            dim3 g(SS/128, SS/128, HH);
            sgemm_k<true><<<g, 256>>>(
                pQ + (long)b * SS * DD, pK + (long)b * SS * DD,
                psc + (long)b * HH * SS * SS,
                SS, SS, DHH, DD, DD, SS,
                DHH, DHH, (long)SS * SS, inv_sqrt_dh);
        }
        k_asmax<<<BB * HH * SS, 256>>>(psc);
        // out = P @ V  (B operand = Vt, K-major)
        for (int b = 0; b < BB; b++) {
            dim3 g(1, SS/128, HH);
            sgemm_k<true><<<g, 256>>>(
                psc + (long)b * HH * SS * SS, pVt + (long)b * SS,
                pao + (long)b * SS * DD,
                SS, DHH, SS, SS, BSZ, DD,
                (long)SS * SS, (long)DHH * BSZ, DHH, 1.f);
        }
        // x += ao @ eo^T
        k_cvt<<<(BSZ * DD) / 256, 256>>>(pao, paoh, paol, (long)BSZ * DD);
        mma_gemm<true><<<dim3(DD/128, BSZ/128), 256, SMEM_MMA>>>(
            paoh, paol, peoh + ooff, peol + ooff, px, DD, DD, DD, DD, 1.f);

        // ---- memory sublayer ----
        k_ln<<<BSZ, 256>>>(px, ln2_g + l * DD, ln2_b + l * DD, pxln, pxlnh, pxlnl);
        mma_gemm<false><<<dim3(NCR/128, BSZ/128), 256, SMEM_MMA>>>(
            pxlnh, pxlnl, pneuh, pneul, pT, DD, DD, DD, NCR, 1.f);
        k_router<<<BSZ/8, 256>>>(pxln, rM, prw);
        k_smax64<<<BSZ, 64>>>(prw);
        k_combine<<<BSZ, 256>>>(pT, prw, ph, phh, phl);
        mma_gemm<false><<<dim3(NKK/128, BSZ/128), 256, SMEM_MMA>>>(
            phh, phl, pkKh, pkKl, pms, RR, RR, RR, NKK, inv_sqrt_r);
        k_topk<<<BSZ, 256>>>(pms, pti, ptw);
        k_memout<<<BSZ, 256>>>(kV, pti, ptw, px);
    }

    // final LN + tied lm head
    k_ln<<<BSZ, 256>>>(px, lnf_g, lnf_b, pxln, pxlnh, pxlnl);
    mma_gemm<false><<<dim3(VV/128, BSZ/128), 256, SMEM_MMA>>>(
        pxlnh, pxlnl, ptembh, ptembl, out, DD, DD, DD, VV, 1.f);
}

// round 7
// speedup vs baseline: 2.2452x; 1.1842x over previous
#include <cuda_runtime.h>
#include <cuda_bf16.h>
#include <cstdint>
#include <math.h>

// Problem dims
#define BB   2
#define SS   1024
#define VV   32000
#define DD   1024
#define RR   256
#define NCC  64
#define NKK  4096
#define KKK  8
#define HH   16
#define LL   4
#define DHH  64
#define BSZ  (BB*SS)          // 2048
#define NCR  (NCC*RR)         // 16384

// ---------------------------------------------------------------------------
// portable helpers (sm_80+ ISA only)
// ---------------------------------------------------------------------------
__device__ __forceinline__ uint32_t smem_to_u32(const void* p) {
    uint32_t a;
    asm("{ .reg .u64 t; cvta.to.shared.u64 t, %1; cvt.u32.u64 %0, t; }" : "=r"(a) : "l"(p));
    return a;
}
#define CP_ASYNC16(saddr, gptr) \
    asm volatile("cp.async.cg.shared.global [%0], [%1], 16;" :: "r"(saddr), "l"(gptr))
#define CP_COMMIT()  asm volatile("cp.async.commit_group;" ::: "memory")
#define CP_WAIT(n)   asm volatile("cp.async.wait_group %0;" :: "n"(n) : "memory")
#define LDSM4(r, a) \
    asm volatile("ldmatrix.sync.aligned.m8n8.x4.shared.b16 {%0,%1,%2,%3}, [%4];" \
        : "=r"((r)[0]), "=r"((r)[1]), "=r"((r)[2]), "=r"((r)[3]) : "r"(a))

__device__ __forceinline__ void mma16816(float* d, const uint32_t* a, const uint32_t* b) {
    asm volatile(
        "mma.sync.aligned.m16n8k16.row.col.f32.bf16.bf16.f32 "
        "{%0,%1,%2,%3}, {%4,%5,%6,%7}, {%8,%9}, {%0,%1,%2,%3};"
        : "+f"(d[0]), "+f"(d[1]), "+f"(d[2]), "+f"(d[3])
        : "r"(a[0]), "r"(a[1]), "r"(a[2]), "r"(a[3]), "r"(b[0]), "r"(b[1]));
}

__device__ __forceinline__ void split_hl(float v, __nv_bfloat16* ph, __nv_bfloat16* pl) {
    __nv_bfloat16 h = __float2bfloat16(v);
    *ph = h;
    *pl = __float2bfloat16(v - __bfloat162float(h));
}

// ---------------- scratch (device globals; allocation-free) ----------------
__device__ float g_x   [BSZ*DD];
__device__ float g_xln [BSZ*DD];
__device__ __nv_bfloat16 g_xlnh[BSZ*DD];
__device__ __nv_bfloat16 g_xlnl[BSZ*DD];
__device__ __nv_bfloat16 g_neuh[(long)NCR*DD];   // neurons^T [NC*R, D] hi
__device__ __nv_bfloat16 g_neul[(long)NCR*DD];
__device__ float g_T   [(long)BSZ*NCR];
__device__ float g_rw  [BSZ*NCC];
__device__ __nv_bfloat16 g_hh[BSZ*RR];
__device__ __nv_bfloat16 g_hl[BSZ*RR];
__device__ __nv_bfloat16 g_Qh[BSZ*DD], g_Ql[BSZ*DD];
__device__ __nv_bfloat16 g_Kh[BSZ*DD], g_Kl[BSZ*DD];
__device__ __nv_bfloat16 g_Vth[DD*BSZ], g_Vtl[DD*BSZ];   // V^T [D, B*S]
__device__ float g_sc  [(long)BB*HH*SS*SS];
__device__ __nv_bfloat16 g_Ph[(long)BB*HH*SS*SS];
__device__ __nv_bfloat16 g_Pl[(long)BB*HH*SS*SS];
__device__ __nv_bfloat16 g_aoh[BSZ*DD], g_aol[BSZ*DD];
__device__ float g_ms  [BSZ*NKK];
__device__ int   g_ti  [BSZ*KKK];
__device__ float g_tw  [BSZ*KKK];
// weight hi/lo splits
__device__ __nv_bfloat16 g_tembh[(long)VV*DD];
__device__ __nv_bfloat16 g_templ[(long)VV*DD];
__device__ __nv_bfloat16 g_eqh[LL*DD*RR], g_eql[LL*DD*RR];
__device__ __nv_bfloat16 g_ekh[LL*DD*RR], g_ekl[LL*DD*RR];
__device__ __nv_bfloat16 g_evh[LL*DD*RR], g_evl[LL*DD*RR];
__device__ __nv_bfloat16 g_eoh[LL*DD*DD], g_eol[LL*DD*DD];
__device__ __nv_bfloat16 g_kKh[NKK*RR],  g_kKl[NKK*RR];

// ---------------------------------------------------------------------------
// warp-MMA GEMM: C[M,N] (+)= alpha * (A[M,K] @ B[N,K]^T), bf16 hi/lo 3-pass.
// A row-major [M,K] stride lda; B [N,K] stride ldb. K%32==0, M%128==0, N%BN==0.
// OUT: 0 = fp32 C (ACC optional), 1 = bf16 hi/lo split to Ch/Cl.
// Batched via blockIdx.z with element strides sA/sB/sC.
// grid = (N/BN, M/128, batch), 256 threads (8 warps: 4 in M x 2 in N).
// ---------------------------------------------------------------------------
#define SKP 40                              // padded row stride (bf16 elems)
#define ABYTES (128*SKP*2)
#define SMEM_FOR(BN_) (4*ABYTES + 4*(BN_)*SKP*2)

template<int BN>
__device__ __forceinline__ void stage_load(
    const __nv_bfloat16* __restrict__ Ah, const __nv_bfloat16* __restrict__ Al,
    const __nv_bfloat16* __restrict__ Bh, const __nv_bfloat16* __restrict__ Bl,
    uint32_t sAh, uint32_t sAl, uint32_t sBh, uint32_t sBl,
    int t, int m0, int n0, int k0, int lda, int ldb)
{
#pragma unroll
    for (int i = 0; i < 2; i++) {           // A: 128 rows x 4 16B-chunks
        int f   = t + (i << 8);
        int row = f >> 2;
        int cc  = (f & 3) << 3;
        uint32_t so = (uint32_t)(row * SKP + cc) * 2;
        long ao_ = (long)(m0 + row) * lda + k0 + cc;
        CP_ASYNC16(sAh + so, Ah + ao_);
        CP_ASYNC16(sAl + so, Al + ao_);
    }
#pragma unroll
    for (int i = 0; i < BN / 64; i++) {     // B: BN rows x 4 chunks
        int f   = t + (i << 8);
        int row = f >> 2;
        int cc  = (f & 3) << 3;
        uint32_t so = (uint32_t)(row * SKP + cc) * 2;
        long bo_ = (long)(n0 + row) * ldb + k0 + cc;
        CP_ASYNC16(sBh + so, Bh + bo_);
        CP_ASYNC16(sBl + so, Bl + bo_);
    }
}

template<int BN, int OUT, bool ACC>
__global__ __launch_bounds__(256)
void mma_gemm(const __nv_bfloat16* __restrict__ Ah, const __nv_bfloat16* __restrict__ Al,
              const __nv_bfloat16* __restrict__ Bh, const __nv_bfloat16* __restrict__ Bl,
              float* __restrict__ C, __nv_bfloat16* __restrict__ Ch, __nv_bfloat16* __restrict__ Cl,
              int K, int lda, int ldb, int ldc,
              long sA, long sB, long sC, float alpha)
{
    constexpr int NT = BN / 16;             // n8-tiles per warp (8 or 4)
    constexpr int NPAIR = NT / 2;
    constexpr uint32_t BBYTES = (uint32_t)BN * SKP * 2;

    extern __shared__ __align__(16) char smem_raw[];
    uint32_t base = smem_to_u32(smem_raw);
    uint32_t sAh0 = base;
    uint32_t sAl0 = base + 2 * ABYTES;
    uint32_t sBh0 = base + 4 * ABYTES;
    uint32_t sBl0 = base + 4 * ABYTES + 2 * BBYTES;

    const int z = blockIdx.z;
    Ah += (long)z * sA; Al += (long)z * sA;
    Bh += (long)z * sB; Bl += (long)z * sB;

    const int t    = threadIdx.x;
    const int lane = t & 31;
    const int wid  = t >> 5;
    const int wm   = (wid & 3) << 5;        // 0/32/64/96
    const int wn   = (wid >> 2) * (BN >> 1);// 0 / BN/2
    const int m0   = blockIdx.y << 7;
    const int n0   = blockIdx.x * BN;

    float acc[2][NT][4];
#pragma unroll
    for (int mt = 0; mt < 2; mt++)
#pragma unroll
        for (int nt = 0; nt < NT; nt++)
#pragma unroll
            for (int j = 0; j < 4; j++) acc[mt][nt][j] = 0.f;

    // ldmatrix lane address offsets (elements)
    const int rA_off = (lane & 7) + ((lane >> 3) & 1) * 8;
    const int cA_off = (lane >> 4) * 8;
    const int rB_off = (lane & 7) + (lane >> 4) * 8;
    const int cB_off = ((lane >> 3) & 1) * 8;
    const uint32_t aBase = (uint32_t)((wm + rA_off) * SKP + cA_off) * 2;
    const uint32_t bBase = (uint32_t)((wn + rB_off) * SKP + cB_off) * 2;

    const int P = K >> 5;
    stage_load<BN>(Ah, Al, Bh, Bl, sAh0, sAl0, sBh0, sBl0, t, m0, n0, 0, lda, ldb);
    CP_COMMIT();

    for (int p = 0; p < P; p++) {
        int s = p & 1;
        if (p + 1 < P) {
            int s2 = (p + 1) & 1;
            stage_load<BN>(Ah, Al, Bh, Bl,
                           sAh0 + s2*ABYTES, sAl0 + s2*ABYTES,
                           sBh0 + s2*BBYTES, sBl0 + s2*BBYTES,
                           t, m0, n0, (p + 1) << 5, lda, ldb);
            CP_COMMIT();
            CP_WAIT(1);
        } else {
            CP_WAIT(0);
        }
        __syncthreads();

        uint32_t bAh = sAh0 + s*ABYTES + aBase, bAl = sAl0 + s*ABYTES + aBase;
        uint32_t bBh = sBh0 + s*BBYTES + bBase, bBl = sBl0 + s*BBYTES + bBase;

#pragma unroll
        for (int ks = 0; ks < 2; ks++) {
            const uint32_t ko = (uint32_t)(ks * 16 * 2);
            uint32_t ah[2][4], al_[2][4];
#pragma unroll
            for (int mt = 0; mt < 2; mt++) {
                uint32_t ro = (uint32_t)(mt * 16 * SKP * 2);
                LDSM4(ah[mt],  bAh + ro + ko);
                LDSM4(al_[mt], bAl + ro + ko);
            }
#pragma unroll
            for (int pr = 0; pr < NPAIR; pr++) {
                uint32_t ro = (uint32_t)(pr * 16 * SKP * 2);
                uint32_t bh[4], bl[4];
                LDSM4(bh, bBh + ro + ko);
                LDSM4(bl, bBl + ro + ko);
#pragma unroll
                for (int mt = 0; mt < 2; mt++) {
                    mma16816(acc[mt][2*pr],   ah[mt],  bh);
                    mma16816(acc[mt][2*pr],   ah[mt],  bl);
                    mma16816(acc[mt][2*pr],   al_[mt], bh);
                    mma16816(acc[mt][2*pr+1], ah[mt],  bh + 2);
                    mma16816(acc[mt][2*pr+1], ah[mt],  bl + 2);
                    mma16816(acc[mt][2*pr+1], al_[mt], bh + 2);
                }
            }
        }
        __syncthreads();
    }

    // epilogue: c0,c1 -> (r, c..c+1); c2,c3 -> (r+8, c..c+1)
    const int rE = lane >> 2;
    const int cE = (lane & 3) << 1;
#pragma unroll
    for (int mt = 0; mt < 2; mt++) {
        int r = m0 + wm + (mt << 4) + rE;
#pragma unroll
        for (int nt = 0; nt < NT; nt++) {
            int c = n0 + wn + (nt << 3) + cE;
            float v0 = acc[mt][nt][0] * alpha, v1 = acc[mt][nt][1] * alpha;
            float v2 = acc[mt][nt][2] * alpha, v3 = acc[mt][nt][3] * alpha;
            if (OUT == 0) {
                float* p0 = C + (long)z * sC + (long)r * ldc + c;
                float* p1 = p0 + 8 * ldc;
                float2 a0 = make_float2(v0, v1), a1 = make_float2(v2, v3);
                if (ACC) {
                    float2 o0 = *(float2*)p0, o1 = *(float2*)p1;
                    a0.x += o0.x; a0.y += o0.y; a1.x += o1.x; a1.y += o1.y;
                }
                *(float2*)p0 = a0;
                *(float2*)p1 = a1;
            } else {
                long o0 = (long)z * sC + (long)r * ldc + c;
                long o1 = o0 + 8 * ldc;
                __nv_bfloat162 h2, l2;
                __nv_bfloat16 hb, lb;
                split_hl(v0, &hb, &lb); h2.x = hb; l2.x = lb;
                split_hl(v1, &hb, &lb); h2.y = hb; l2.y = lb;
                *(__nv_bfloat162*)(Ch + o0) = h2;
                *(__nv_bfloat162*)(Cl + o0) = l2;
                split_hl(v2, &hb, &lb); h2.x = hb; l2.x = lb;
                split_hl(v3, &hb, &lb); h2.y = hb; l2.y = lb;
                *(__nv_bfloat162*)(Ch + o1) = h2;
                *(__nv_bfloat162*)(Cl + o1) = l2;
            }
        }
    }
}

// ---------------------------------------------------------------------------
// small kernels
// ---------------------------------------------------------------------------
// neurons [NC,D,R] -> neuT [NC*R, D] bf16 hi/lo (tiled transpose)
__global__ void k_neuT(const float* __restrict__ nn,
                       __nv_bfloat16* __restrict__ oh, __nv_bfloat16* __restrict__ ol)
{
    __shared__ float tile[32][33];
    int d0 = blockIdx.x * 32, r0 = blockIdx.y * 32, n = blockIdx.z;
    int tx = threadIdx.x, ty = threadIdx.y;
#pragma unroll
    for (int j = 0; j < 32; j += 8)
        tile[ty + j][tx] = nn[((long)n * DD + d0 + ty + j) * RR + r0 + tx];
    __syncthreads();
#pragma unroll
    for (int j = 0; j < 32; j += 8) {
        float v = tile[tx][ty + j];
        long o = ((long)(n * RR + r0 + ty + j)) * DD + d0 + tx;
        split_hl(v, oh + o, ol + o);
    }
}

__global__ void k_cvt(const float* __restrict__ x, __nv_bfloat16* __restrict__ h,
                      __nv_bfloat16* __restrict__ l, long n)
{
    long i = (long)blockIdx.x * 256 + threadIdx.x;
    if (i < n) split_hl(x[i], h + i, l + i);
}

__global__ void k_embed(const int* __restrict__ tokens, const float* __restrict__ te,
                        const float* __restrict__ pe, float* __restrict__ x)
{
    int s = blockIdx.x;
    int tok = tokens[s];
    int sp  = s & (SS - 1);
    const float* tr = te + (long)tok * DD;
    const float* pr = pe + (long)sp * DD;
    float* xr = x + (long)s * DD;
    for (int d = threadIdx.x; d < DD; d += blockDim.x)
        xr[d] = tr[d] + pr[d];
}

__global__ void k_ln(const float* __restrict__ x, const float* __restrict__ g,
                     const float* __restrict__ b, float* __restrict__ y,
                     __nv_bfloat16* __restrict__ yh, __nv_bfloat16* __restrict__ yl)
{
    int s = blockIdx.x, t = threadIdx.x;
    __shared__ float row[DD];
    __shared__ float red[256];
    const float* xr = x + (long)s * DD;
    float ls = 0.f;
    for (int d = t; d < DD; d += 256) { float v = xr[d]; row[d] = v; ls += v; }
    red[t] = ls; __syncthreads();
    for (int o = 128; o > 0; o >>= 1) { if (t < o) red[t] += red[t + o]; __syncthreads(); }
    float mean = red[0] * (1.f / DD); __syncthreads();
    float lv = 0.f;
    for (int d = t; d < DD; d += 256) { float dv = row[d] - mean; lv += dv * dv; }
    red[t] = lv; __syncthreads();
    for (int o = 128; o > 0; o >>= 1) { if (t < o) red[t] += red[t + o]; __syncthreads(); }
    float rstd = rsqrtf(red[0] * (1.f / DD) + 1e-5f);
    for (int d = t; d < DD; d += 256) {
        float v = (row[d] - mean) * rstd * g[d] + b[d];
        long o = (long)s * DD + d;
        y[o] = v;
        split_hl(v, yh + o, yl + o);
    }
}

// router logits: rw[s, n] = sum_d xln[s,d] * R_[n,d]  (N = 64)
__global__ void k_router(const float* __restrict__ xln, const float* __restrict__ R_,
                         float* __restrict__ rw)
{
    __shared__ float xs[8][DD];
    int s0 = blockIdx.x * 8;
    for (int i = threadIdx.x; i < 2048; i += 256) {
        int r = i >> 8, c = (i & 255) << 2;
        *(float4*)&xs[r][c] = *(const float4*)(xln + (long)(s0 + r) * DD + c);
    }
    __syncthreads();
    int w = threadIdx.x >> 5, lane = threadIdx.x & 31;
    for (int n = 0; n < NCC; n++) {
        const float* rr = R_ + (long)n * DD;
        float acc = 0.f;
        for (int k = lane * 4; k < DD; k += 128) {
            float4 rv = *(const float4*)(rr + k);
            float4 xv = *(const float4*)&xs[w][k];
            acc += rv.x * xv.x + rv.y * xv.y + rv.z * xv.z + rv.w * xv.w;
        }
#pragma unroll
        for (int o = 16; o; o >>= 1) acc += __shfl_xor_sync(0xFFFFFFFFu, acc, o);
        if (!lane) rw[(long)(s0 + w) * NCC + n] = acc;
    }
}

__global__ void k_smax64(float* __restrict__ a)
{
    int s = blockIdx.x, t = threadIdx.x;
    __shared__ float m[64];
    float v = a[(long)s * NCC + t];
    m[t] = v; __syncthreads();
    for (int o = 32; o > 0; o >>= 1) { if (t < o) m[t] = fmaxf(m[t], m[t + o]); __syncthreads(); }
    float mx = m[0]; __syncthreads();
    float e = expf(v - mx);
    m[t] = e; __syncthreads();
    for (int o = 32; o > 0; o >>= 1) { if (t < o) m[t] += m[t + o]; __syncthreads(); }
    a[(long)s * NCC + t] = e / m[0];
}

// h[s,r] = sum_n w[s,n] * T[s, n*R + r] -> bf16 hi/lo
__global__ void k_combine(const float* __restrict__ T, const float* __restrict__ w,
                          __nv_bfloat16* __restrict__ hh, __nv_bfloat16* __restrict__ hl)
{
    int s = blockIdx.x, r = threadIdx.x;
    __shared__ float ws[NCC];
    if (r < NCC) ws[r] = w[(long)s * NCC + r];
    __syncthreads();
    const float* Trow = T + (long)s * NCR;
    float acc = 0.f;
#pragma unroll 8
    for (int n = 0; n < NCC; n++)
        acc += ws[n] * Trow[n * RR + r];
    long o = (long)s * RR + r;
    split_hl(acc, hh + o, hl + o);
}

// causal softmax: read fp32 scores, write P as bf16 hi/lo (zero tail)
__global__ void k_asmax(const float* __restrict__ sc,
                        __nv_bfloat16* __restrict__ Ph, __nv_bfloat16* __restrict__ Pl)
{
    int rrow = blockIdx.x;
    int q = rrow & (SS - 1);
    int t = threadIdx.x;
    __shared__ float row[SS];
    __shared__ float red[256];
    const float* p = sc + (long)rrow * SS;
    int len = q + 1;
    float lm = -1e30f;
    for (int d = t; d < len; d += 256) { float v = p[d]; row[d] = v; lm = fmaxf(lm, v); }
    red[t] = lm; __syncthreads();
    for (int o = 128; o > 0; o >>= 1) { if (t < o) red[t] = fmaxf(red[t], red[t + o]); __syncthreads(); }
    float mx = red[0]; __syncthreads();
    float lsum = 0.f;
    for (int d = t; d < len; d += 256) { float e = expf(row[d] - mx); row[d] = e; lsum += e; }
    red[t] = lsum; __syncthreads();
    for (int o = 128; o > 0; o >>= 1) { if (t < o) red[t] += red[t + o]; __syncthreads(); }
    float inv = 1.f / red[0];
    long off = (long)rrow * SS;
    for (int d = t; d < SS; d += 256) {
        float v = (d < len) ? row[d] * inv : 0.f;
        split_hl(v, Ph + off + d, Pl + off + d);
    }
}

__global__ void k_topk(const float* __restrict__ sc, int* __restrict__ ti, float* __restrict__ tw)
{
    __shared__ float row[NKK];
    __shared__ float rv[256];
    __shared__ int   ri[256];
    __shared__ float selv[KKK];
    __shared__ int   seli[KKK];
    int s = blockIdx.x, t = threadIdx.x;
    const float* p = sc + (long)s * NKK;
    for (int i = t; i < NKK; i += 256) row[i] = p[i];
    __syncthreads();
    for (int it = 0; it < KKK; it++) {
        float bm = -1e30f; int bi = NKK;
        for (int i = t; i < NKK; i += 256)
            if (row[i] > bm) { bm = row[i]; bi = i; }
        rv[t] = bm; ri[t] = bi; __syncthreads();
        for (int o = 128; o > 0; o >>= 1) {
            if (t < o) {
                if (rv[t + o] > rv[t] || (rv[t + o] == rv[t] && ri[t + o] < ri[t])) {
                    rv[t] = rv[t + o]; ri[t] = ri[t + o];
                }
            }
            __syncthreads();
        }
        if (t == 0) { selv[it] = rv[0]; seli[it] = ri[0]; row[ri[0]] = -1e30f; }
        __syncthreads();
    }
    if (t == 0) {
        float mx = selv[0];
        float e[KKK], sum = 0.f;
#pragma unroll
        for (int j = 0; j < KKK; j++) { e[j] = expf(selv[j] - mx); sum += e[j]; }
        float inv = 1.f / sum;
#pragma unroll
        for (int j = 0; j < KKK; j++) { tw[(long)s * KKK + j] = e[j] * inv; ti[(long)s * KKK + j] = seli[j]; }
    }
}

__global__ void k_memout(const float* __restrict__ kV, const int* __restrict__ ti,
                         const float* __restrict__ tw, float* __restrict__ x)
{
    int s = blockIdx.x, t = threadIdx.x;
    __shared__ int   idx[KKK];
    __shared__ float w[KKK];
    if (t < KKK) { idx[t] = ti[(long)s * KKK + t]; w[t] = tw[(long)s * KKK + t]; }
    __syncthreads();
    float* xr = x + (long)s * DD;
    for (int d = t; d < DD; d += 256) {
        float a = xr[d];
#pragma unroll
        for (int j = 0; j < KKK; j++)
            a += w[j] * kV[(long)idx[j] * DD + d];
        xr[d] = a;
    }
}

// ---------------------------------------------------------------------------
extern "C" void kernel_launch(void* const* d_in, const int* in_sizes, int n_in,
                              void* d_out, int out_size)
{
    (void)in_sizes; (void)n_in; (void)out_size;
    const int*   tokens   = (const int*)  d_in[0];
    const float* tok_emb  = (const float*)d_in[1];
    const float* pos_emb  = (const float*)d_in[2];
    const float* neurons  = (const float*)d_in[3];
    const float* kK       = (const float*)d_in[4];
    const float* kV       = (const float*)d_in[5];
    const float* routerQ  = (const float*)d_in[6];
    const float* routerK  = (const float*)d_in[7];
    const float* routerV  = (const float*)d_in[8];
    const float* routerM  = (const float*)d_in[9];
    const float* expQ     = (const float*)d_in[10];
    const float* expK     = (const float*)d_in[11];
    const float* expV     = (const float*)d_in[12];
    const float* expO     = (const float*)d_in[13];
    const float* ln1_g    = (const float*)d_in[14];
    const float* ln1_b    = (const float*)d_in[15];
    const float* ln2_g    = (const float*)d_in[16];
    const float* ln2_b    = (const float*)d_in[17];
    const float* lnf_g    = (const float*)d_in[18];
    const float* lnf_b    = (const float*)d_in[19];
    float* out = (float*)d_out;

    float *px, *pxln, *pT, *prw, *psc, *pms, *ptw;
    int *pti;
    __nv_bfloat16 *pxlnh, *pxlnl, *pneuh, *pneul, *phh, *phl;
    __nv_bfloat16 *pQh, *pQl, *pKh, *pKl, *pVth, *pVtl, *pPh, *pPl, *paoh, *paol;
    __nv_bfloat16 *ptembh, *ptembl, *peqh, *peql, *pekh, *pekl, *pevh, *pevl, *peoh, *peol, *pkKh, *pkKl;
    cudaGetSymbolAddress((void**)&px,    g_x);
    cudaGetSymbolAddress((void**)&pxln,  g_xln);
    cudaGetSymbolAddress((void**)&pxlnh, g_xlnh);
    cudaGetSymbolAddress((void**)&pxlnl, g_xlnl);
    cudaGetSymbolAddress((void**)&pneuh, g_neuh);
    cudaGetSymbolAddress((void**)&pneul, g_neul);
    cudaGetSymbolAddress((void**)&pT,    g_T);
    cudaGetSymbolAddress((void**)&prw,   g_rw);
    cudaGetSymbolAddress((void**)&phh,   g_hh);
    cudaGetSymbolAddress((void**)&phl,   g_hl);
    cudaGetSymbolAddress((void**)&pQh,   g_Qh);
    cudaGetSymbolAddress((void**)&pQl,   g_Ql);
    cudaGetSymbolAddress((void**)&pKh,   g_Kh);
    cudaGetSymbolAddress((void**)&pKl,   g_Kl);
    cudaGetSymbolAddress((void**)&pVth,  g_Vth);
    cudaGetSymbolAddress((void**)&pVtl,  g_Vtl);
    cudaGetSymbolAddress((void**)&psc,   g_sc);
    cudaGetSymbolAddress((void**)&pPh,   g_Ph);
    cudaGetSymbolAddress((void**)&pPl,   g_Pl);
    cudaGetSymbolAddress((void**)&paoh,  g_aoh);
    cudaGetSymbolAddress((void**)&paol,  g_aol);
    cudaGetSymbolAddress((void**)&pms,   g_ms);
    cudaGetSymbolAddress((void**)&pti,   g_ti);
    cudaGetSymbolAddress((void**)&ptw,   g_tw);
    cudaGetSymbolAddress((void**)&ptembh, g_tembh);
    cudaGetSymbolAddress((void**)&ptembl, g_templ);
    cudaGetSymbolAddress((void**)&peqh,  g_eqh);
    cudaGetSymbolAddress((void**)&peql,  g_eql);
    cudaGetSymbolAddress((void**)&pekh,  g_ekh);
    cudaGetSymbolAddress((void**)&pekl,  g_ekl);
    cudaGetSymbolAddress((void**)&pevh,  g_evh);
    cudaGetSymbolAddress((void**)&pevl,  g_evl);
    cudaGetSymbolAddress((void**)&peoh,  g_eoh);
    cudaGetSymbolAddress((void**)&peol,  g_eol);
    cudaGetSymbolAddress((void**)&pkKh,  g_kKh);
    cudaGetSymbolAddress((void**)&pkKl,  g_kKl);

    cudaFuncSetAttribute(mma_gemm<128,0,false>, cudaFuncAttributeMaxDynamicSharedMemorySize, SMEM_FOR(128));
    cudaFuncSetAttribute(mma_gemm<128,0,true>,  cudaFuncAttributeMaxDynamicSharedMemorySize, SMEM_FOR(128));
    cudaFuncSetAttribute(mma_gemm<128,1,false>, cudaFuncAttributeMaxDynamicSharedMemorySize, SMEM_FOR(128));
    cudaFuncSetAttribute(mma_gemm<64,1,false>,  cudaFuncAttributeMaxDynamicSharedMemorySize, SMEM_FOR(64));

    const int SM128 = SMEM_FOR(128);
    const int SM64  = SMEM_FOR(64);

    // one-time weight preprocessing
    k_neuT<<<dim3(DD/32, RR/32, NCC), dim3(32, 8)>>>(neurons, pneuh, pneul);
    {
        long n;
        n = (long)VV * DD;     k_cvt<<<(unsigned)((n + 255) / 256), 256>>>(tok_emb, ptembh, ptembl, n);
        n = (long)LL * DD * RR;
        k_cvt<<<(unsigned)((n + 255) / 256), 256>>>(expQ, peqh, peql, n);
        k_cvt<<<(unsigned)((n + 255) / 256), 256>>>(expK, pekh, pekl, n);
        k_cvt<<<(unsigned)((n + 255) / 256), 256>>>(expV, pevh, pevl, n);
        n = (long)LL * DD * DD; k_cvt<<<(unsigned)((n + 255) / 256), 256>>>(expO, peoh, peol, n);
        n = (long)NKK * RR;     k_cvt<<<(unsigned)((n + 255) / 256), 256>>>(kK, pkKh, pkKl, n);
    }
    k_embed<<<BSZ, 256>>>(tokens, tok_emb, pos_emb, px);

    for (int l = 0; l < LL; l++) {
        const float* rQ = routerQ + (long)l * NCC * DD;
        const float* rK = routerK + (long)l * NCC * DD;
        const float* rV = routerV + (long)l * NCC * DD;
        const float* rM = routerM + (long)l * NCC * DD;
        long eoff = (long)l * DD * RR;
        long ooff = (long)l * DD * DD;

        // ---- attention sublayer ----
        k_ln<<<BSZ, 256>>>(px, ln1_g + l * DD, ln1_b + l * DD, pxln, pxlnh, pxlnl);
        mma_gemm<128,0,false><<<dim3(NCR/128, BSZ/128, 1), 256, SM128>>>(
            pxlnh, pxlnl, pneuh, pneul, pT, nullptr, nullptr,
            DD, DD, DD, NCR, 0, 0, 0, 1.f);

        // Q
        k_router<<<BSZ/8, 256>>>(pxln, rQ, prw);
        k_smax64<<<BSZ, 64>>>(prw);
        k_combine<<<BSZ, 256>>>(pT, prw, phh, phl);
        mma_gemm<128,1,false><<<dim3(DD/128, BSZ/128, 1), 256, SM128>>>(
            phh, phl, peqh + eoff, peql + eoff, nullptr, pQh, pQl,
            RR, RR, RR, DD, 0, 0, 0, 1.f);
        // K
        k_router<<<BSZ/8, 256>>>(pxln, rK, prw);
        k_smax64<<<BSZ, 64>>>(prw);
        k_combine<<<BSZ, 256>>>(pT, prw, phh, phl);
        mma_gemm<128,1,false><<<dim3(DD/128, BSZ/128, 1), 256, SM128>>>(
            phh, phl, pekh + eoff, pekl + eoff, nullptr, pKh, pKl,
            RR, RR, RR, DD, 0, 0, 0, 1.f);
        // V (transposed: Vt[D, B*S] = ev @ h^T)
        k_router<<<BSZ/8, 256>>>(pxln, rV, prw);
        k_smax64<<<BSZ, 64>>>(prw);
        k_combine<<<BSZ, 256>>>(pT, prw, phh, phl);
        mma_gemm<128,1,false><<<dim3(BSZ/128, DD/128, 1), 256, SM128>>>(
            pevh + eoff, pevl + eoff, phh, phl, nullptr, pVth, pVtl,
            RR, RR, RR, BSZ, 0, 0, 0, 1.f);

        // scores = Q K^T / 8 (batched over heads, per b)
        for (int b = 0; b < BB; b++) {
            mma_gemm<128,0,false><<<dim3(SS/128, SS/128, HH), 256, SM128>>>(
                pQh + (long)b * SS * DD, pQl + (long)b * SS * DD,
                pKh + (long)b * SS * DD, pKl + (long)b * SS * DD,
                psc + (long)b * HH * SS * SS, nullptr, nullptr,
                DHH, DD, DD, SS,
                (long)DHH, (long)DHH, (long)SS * SS, 0.125f);
        }
        k_asmax<<<BB * HH * SS, 256>>>(psc, pPh, pPl);
        // ao = P @ V  (B operand = Vt rows h*64.., K-major)
        for (int b = 0; b < BB; b++) {
            mma_gemm<64,1,false><<<dim3(1, SS/128, HH), 256, SM64>>>(
                pPh + (long)b * HH * SS * SS, pPl + (long)b * HH * SS * SS,
                pVth + (long)b * SS, pVtl + (long)b * SS,
                nullptr, paoh + (long)b * SS * DD, paol + (long)b * SS * DD,
                SS, SS, BSZ, DD,
                (long)SS * SS, (long)DHH * BSZ, (long)DHH, 1.f);
        }
        // x += ao @ eo^T
        mma_gemm<128,0,true><<<dim3(DD/128, BSZ/128, 1), 256, SM128>>>(
            paoh, paol, peoh + ooff, peol + ooff, px, nullptr, nullptr,
            DD, DD, DD, DD, 0, 0, 0, 1.f);

        // ---- memory sublayer ----
        k_ln<<<BSZ, 256>>>(px, ln2_g + l * DD, ln2_b + l * DD, pxln, pxlnh, pxlnl);
        mma_gemm<128,0,false><<<dim3(NCR/128, BSZ/128, 1), 256, SM128>>>(
            pxlnh, pxlnl, pneuh, pneul, pT, nullptr, nullptr,
            DD, DD, DD, NCR, 0, 0, 0, 1.f);
        k_router<<<BSZ/8, 256>>>(pxln, rM, prw);
        k_smax64<<<BSZ, 64>>>(prw);
        k_combine<<<BSZ, 256>>>(pT, prw, phh, phl);
        mma_gemm<128,0,false><<<dim3(NKK/128, BSZ/128, 1), 256, SM128>>>(
            phh, phl, pkKh, pkKl, pms, nullptr, nullptr,
            RR, RR, RR, NKK, 0, 0, 0, 0.0625f);
        k_topk<<<BSZ, 256>>>(pms, pti, ptw);
        k_memout<<<BSZ, 256>>>(kV, pti, ptw, px);
    }

    // final LN + tied lm head
    k_ln<<<BSZ, 256>>>(px, lnf_g, lnf_b, pxln, pxlnh, pxlnl);
    mma_gemm<128,0,false><<<dim3(VV/128, BSZ/128, 1), 256, SM128>>>(
        pxlnh, pxlnl, ptembh, ptembl, out, nullptr, nullptr,
        DD, DD, DD, VV, 0, 0, 0, 1.f);
}